// round 4
// baseline (speedup 1.0000x reference)
#include <cuda_runtime.h>
#include <math.h>

#define N_NODES 100000
#define C_DIM   128
#define E_EDGES 1600000

typedef unsigned long long u64;

// ---- scratch (static __device__, no allocation) ----
__device__ float g_wnew[C_DIM * C_DIM];
__device__ float g_xs[(size_t)N_NODES * C_DIM];   // (x @ w_new) * dinv[row]
__device__ int   g_deg[N_NODES];
__device__ float g_dinv[N_NODES];

// ---- packed f32x2 helpers (FFMA2 path: ptxas never auto-fuses this) ----
__device__ __forceinline__ u64 pack2(float lo, float hi) {
    u64 r;
    asm("mov.b64 %0, {%1, %2};" : "=l"(r) : "f"(lo), "f"(hi));
    return r;
}
__device__ __forceinline__ void fma2(u64& d, u64 a, u64 b) {
    asm("fma.rn.f32x2 %0, %1, %2, %0;" : "+l"(d) : "l"(a), "l"(b));
}
__device__ __forceinline__ float2 unpack2(u64 v) {
    float2 f;
    asm("mov.b64 {%0, %1}, %2;" : "=f"(f.x), "=f"(f.y) : "l"(v));
    return f;
}

// ---------------------------------------------------------------------------
// Kernel 1: LSTM single step -> evolved GCN weight w_new [C,C]
// ---------------------------------------------------------------------------
__global__ void k_wnew(const float* __restrict__ weight,
                       const float* __restrict__ w_ih,
                       const float* __restrict__ b_ih,
                       const float* __restrict__ b_hh) {
    __shared__ __align__(16) float wrow[C_DIM];
    const int r = blockIdx.x;
    const int c = threadIdx.x;
    wrow[c] = weight[r * C_DIM + c];
    __syncthreads();

    const float4* wr4 = (const float4*)wrow;
    const float4* wi  = (const float4*)(w_ih + (size_t)(c) * C_DIM);
    const float4* wg  = (const float4*)(w_ih + (size_t)(2 * C_DIM + c) * C_DIM);
    const float4* wo  = (const float4*)(w_ih + (size_t)(3 * C_DIM + c) * C_DIM);

    float di = 0.f, dg = 0.f, dob = 0.f;
#pragma unroll
    for (int q = 0; q < C_DIM / 4; q++) {
        const float4 w4 = wr4[q];
        const float4 a = wi[q];
        const float4 b = wg[q];
        const float4 d = wo[q];
        di  = fmaf(w4.x, a.x, fmaf(w4.y, a.y, fmaf(w4.z, a.z, fmaf(w4.w, a.w, di))));
        dg  = fmaf(w4.x, b.x, fmaf(w4.y, b.y, fmaf(w4.z, b.z, fmaf(w4.w, b.w, dg))));
        dob = fmaf(w4.x, d.x, fmaf(w4.y, d.y, fmaf(w4.z, d.z, fmaf(w4.w, d.w, dob))));
    }
    const float iv = di  + b_ih[c]             + b_hh[c];
    const float gv = dg  + b_ih[2 * C_DIM + c] + b_hh[2 * C_DIM + c];
    const float ov = dob + b_ih[3 * C_DIM + c] + b_hh[3 * C_DIM + c];

    const float sig_i = 1.f / (1.f + __expf(-iv));
    const float sig_o = 1.f / (1.f + __expf(-ov));
    const float cst   = sig_i * tanhf(gv);
    g_wnew[r * C_DIM + c] = sig_o * tanhf(cst);
}

// ---------------------------------------------------------------------------
// Degree / norm kernels
// ---------------------------------------------------------------------------
__global__ void k_deg_init() {
    const int i = blockIdx.x * blockDim.x + threadIdx.x;
    if (i < N_NODES) g_deg[i] = 1;   // self-loop
}

__global__ void k_deg_count(const int* __restrict__ dst) {
    const int e = blockIdx.x * blockDim.x + threadIdx.x;
    if (e < E_EDGES) atomicAdd(&g_deg[dst[e]], 1);
}

__global__ void k_dinv() {
    const int i = blockIdx.x * blockDim.x + threadIdx.x;
    if (i < N_NODES) g_dinv[i] = rsqrtf((float)g_deg[i]);
}

// ---------------------------------------------------------------------------
// GEMM via packed f32x2 FMA (FFMA2): xw = x @ w_new,
//   xs = xw*dinv[row] -> scratch; out[row] = xs*dinv[row] (self-loop init).
// 128x128 tile per block, 8 rows x 8 cols per thread, cols held as 4 f32x2.
// ---------------------------------------------------------------------------
__global__ void __launch_bounds__(256, 2)
k_gemm(const float* __restrict__ x, float* __restrict__ out) {
    extern __shared__ float Ws[];   // 128*128 floats = 64KB

    {
        float4* Ws4 = (float4*)Ws;
        const float4* W4 = (const float4*)g_wnew;
        for (int i = threadIdx.x; i < (C_DIM * C_DIM) / 4; i += 256)
            Ws4[i] = W4[i];
    }
    __syncthreads();

    const int tx = threadIdx.x & 15;          // col group
    const int ty = threadIdx.x >> 4;          // row group
    const int row0 = blockIdx.x * 128 + ty * 8;
    const int col0 = tx * 8;

    const float* xp[8];
#pragma unroll
    for (int i = 0; i < 8; i++) {
        int r = row0 + i;
        if (r >= N_NODES) r = N_NODES - 1;    // clamp (stores guarded later)
        xp[i] = x + (size_t)r * C_DIM;
    }

    u64 acc[8][4];
#pragma unroll
    for (int i = 0; i < 8; i++)
#pragma unroll
        for (int j = 0; j < 4; j++) acc[i][j] = 0ull;

    for (int k0 = 0; k0 < C_DIM; k0 += 4) {
        float4 xv[8];
#pragma unroll
        for (int i = 0; i < 8; i++)
            xv[i] = *(const float4*)(xp[i] + k0);

#pragma unroll
        for (int j = 0; j < 4; j++) {
            const int k = k0 + j;
            // 8 weight cols = 4 packed f32x2, loaded as two 16B LDS
            const ulonglong2 wA = *(const ulonglong2*)(Ws + k * C_DIM + col0);
            const ulonglong2 wB = *(const ulonglong2*)(Ws + k * C_DIM + col0 + 4);
#pragma unroll
            for (int i = 0; i < 8; i++) {
                const float xk = ((const float*)&xv[i])[j];
                const u64 xkk = pack2(xk, xk);
                fma2(acc[i][0], xkk, wA.x);
                fma2(acc[i][1], xkk, wA.y);
                fma2(acc[i][2], xkk, wB.x);
                fma2(acc[i][3], xkk, wB.y);
            }
        }
    }

#pragma unroll
    for (int i = 0; i < 8; i++) {
        const int r = row0 + i;
        if (r < N_NODES) {
            const float dv = g_dinv[r];
            const float dv2 = dv * dv;
            float a[8];
#pragma unroll
            for (int j = 0; j < 4; j++) {
                const float2 f = unpack2(acc[i][j]);
                a[2 * j] = f.x;
                a[2 * j + 1] = f.y;
            }
            float4 s0, s1, o0, o1;
            s0.x = a[0] * dv; s0.y = a[1] * dv; s0.z = a[2] * dv; s0.w = a[3] * dv;
            s1.x = a[4] * dv; s1.y = a[5] * dv; s1.z = a[6] * dv; s1.w = a[7] * dv;
            o0.x = a[0] * dv2; o0.y = a[1] * dv2; o0.z = a[2] * dv2; o0.w = a[3] * dv2;
            o1.x = a[4] * dv2; o1.y = a[5] * dv2; o1.z = a[6] * dv2; o1.w = a[7] * dv2;
            *(float4*)(g_xs + (size_t)r * C_DIM + col0)     = s0;
            *(float4*)(g_xs + (size_t)r * C_DIM + col0 + 4) = s1;
            *(float4*)(out  + (size_t)r * C_DIM + col0)     = o0;  // self-loop init
            *(float4*)(out  + (size_t)r * C_DIM + col0 + 4) = o1;
        }
    }
}

// ---------------------------------------------------------------------------
// Edge scatter: out[dst] += xs[src] * dinv[dst]   (xs already holds *dinv[src])
// ---------------------------------------------------------------------------
__global__ void k_scatter(const int* __restrict__ srcA,
                          const int* __restrict__ dstA,
                          float* __restrict__ out) {
    const int warp = (blockIdx.x * blockDim.x + threadIdx.x) >> 5;
    const int lane = threadIdx.x & 31;
    const int e0 = warp * 32 + lane;

    int s = 0, d = 0;
    float nrm = 0.f;                       // 0 for out-of-range edges -> adds nothing
    if (e0 < E_EDGES) {
        s = srcA[e0];
        d = dstA[e0];
        nrm = g_dinv[d];
    }

#pragma unroll 4
    for (int i = 0; i < 32; i++) {
        const int   ss = __shfl_sync(0xffffffffu, s, i);
        const int   dd = __shfl_sync(0xffffffffu, d, i);
        const float nn = __shfl_sync(0xffffffffu, nrm, i);

        const float4 v = *(const float4*)(g_xs + (size_t)ss * C_DIM + lane * 4);
        float* p = out + (size_t)dd * C_DIM + lane * 4;
        asm volatile("red.global.add.v4.f32 [%0], {%1, %2, %3, %4};"
                     :: "l"(p), "f"(v.x * nn), "f"(v.y * nn),
                        "f"(v.z * nn), "f"(v.w * nn)
                     : "memory");
    }
}

// ---------------------------------------------------------------------------
// Launch
// inputs: 0:x[N,C] 1:edge_index[2,E] 2:weight[C,C] 3:w_ih[4C,C] 4:w_hh 5:b_ih 6:b_hh
// ---------------------------------------------------------------------------
extern "C" void kernel_launch(void* const* d_in, const int* in_sizes, int n_in,
                              void* d_out, int out_size) {
    const float* x      = (const float*)d_in[0];
    const int*   ei     = (const int*)  d_in[1];
    const float* weight = (const float*)d_in[2];
    const float* w_ih   = (const float*)d_in[3];
    const float* b_ih   = (const float*)d_in[5];
    const float* b_hh   = (const float*)d_in[6];
    float* out = (float*)d_out;

    const int* srcA = ei;
    const int* dstA = ei + E_EDGES;

    k_wnew<<<C_DIM, C_DIM>>>(weight, w_ih, b_ih, b_hh);

    k_deg_init<<<(N_NODES + 255) / 256, 256>>>();
    k_deg_count<<<(E_EDGES + 255) / 256, 256>>>(dstA);
    k_dinv<<<(N_NODES + 255) / 256, 256>>>();

    cudaFuncSetAttribute(k_gemm, cudaFuncAttributeMaxDynamicSharedMemorySize, 65536);
    k_gemm<<<(N_NODES + 127) / 128, 256, 65536>>>(x, out);

    const int warps = (E_EDGES + 31) / 32;          // 50000
    const int blocks = (warps + 7) / 8;             // 256 threads = 8 warps/block
    k_scatter<<<blocks, 256>>>(srcA, dstA, out);
}

// round 5
// speedup vs baseline: 1.0027x; 1.0027x over previous
#include <cuda_runtime.h>
#include <math.h>

#define N_NODES 100000
#define C_DIM   128
#define E_EDGES 1600000

typedef unsigned long long u64;

// ---- scratch (static __device__, no allocation) ----
__device__ float g_wnew[C_DIM * C_DIM];
__device__ float g_xs[(size_t)N_NODES * C_DIM];   // (x @ w_new) * dinv[row]
__device__ int   g_deg[N_NODES];
__device__ float g_dinv[N_NODES];

// ---- packed f32x2 helpers (FFMA2 path: ptxas never auto-fuses this) ----
__device__ __forceinline__ u64 pack2(float lo, float hi) {
    u64 r;
    asm("mov.b64 %0, {%1, %2};" : "=l"(r) : "f"(lo), "f"(hi));
    return r;
}
__device__ __forceinline__ void fma2(u64& d, u64 a, u64 b) {
    asm("fma.rn.f32x2 %0, %1, %2, %0;" : "+l"(d) : "l"(a), "l"(b));
}
__device__ __forceinline__ float2 unpack2(u64 v) {
    float2 f;
    asm("mov.b64 {%0, %1}, %2;" : "=f"(f.x), "=f"(f.y) : "l"(v));
    return f;
}

// ---------------------------------------------------------------------------
// Kernel 1: LSTM single step -> evolved GCN weight w_new [C,C]
// ---------------------------------------------------------------------------
__global__ void k_wnew(const float* __restrict__ weight,
                       const float* __restrict__ w_ih,
                       const float* __restrict__ b_ih,
                       const float* __restrict__ b_hh) {
    __shared__ __align__(16) float wrow[C_DIM];
    const int r = blockIdx.x;
    const int c = threadIdx.x;
    wrow[c] = weight[r * C_DIM + c];
    __syncthreads();

    const float4* wr4 = (const float4*)wrow;
    const float4* wi  = (const float4*)(w_ih + (size_t)(c) * C_DIM);
    const float4* wg  = (const float4*)(w_ih + (size_t)(2 * C_DIM + c) * C_DIM);
    const float4* wo  = (const float4*)(w_ih + (size_t)(3 * C_DIM + c) * C_DIM);

    float di = 0.f, dg = 0.f, dob = 0.f;
#pragma unroll
    for (int q = 0; q < C_DIM / 4; q++) {
        const float4 w4 = wr4[q];
        const float4 a = wi[q];
        const float4 b = wg[q];
        const float4 d = wo[q];
        di  = fmaf(w4.x, a.x, fmaf(w4.y, a.y, fmaf(w4.z, a.z, fmaf(w4.w, a.w, di))));
        dg  = fmaf(w4.x, b.x, fmaf(w4.y, b.y, fmaf(w4.z, b.z, fmaf(w4.w, b.w, dg))));
        dob = fmaf(w4.x, d.x, fmaf(w4.y, d.y, fmaf(w4.z, d.z, fmaf(w4.w, d.w, dob))));
    }
    const float iv = di  + b_ih[c]             + b_hh[c];
    const float gv = dg  + b_ih[2 * C_DIM + c] + b_hh[2 * C_DIM + c];
    const float ov = dob + b_ih[3 * C_DIM + c] + b_hh[3 * C_DIM + c];

    const float sig_i = 1.f / (1.f + __expf(-iv));
    const float sig_o = 1.f / (1.f + __expf(-ov));
    const float cst   = sig_i * tanhf(gv);
    g_wnew[r * C_DIM + c] = sig_o * tanhf(cst);
}

// ---------------------------------------------------------------------------
// Degree / norm kernels
// ---------------------------------------------------------------------------
__global__ void k_deg_init() {
    const int i = blockIdx.x * blockDim.x + threadIdx.x;
    if (i < N_NODES) g_deg[i] = 1;   // self-loop
}

__global__ void k_deg_count(const int* __restrict__ dst) {
    const int e = blockIdx.x * blockDim.x + threadIdx.x;
    if (e < E_EDGES) atomicAdd(&g_deg[dst[e]], 1);
}

__global__ void k_dinv() {
    const int i = blockIdx.x * blockDim.x + threadIdx.x;
    if (i < N_NODES) g_dinv[i] = rsqrtf((float)g_deg[i]);
}

// ---------------------------------------------------------------------------
// GEMM via packed f32x2 FMA (FFMA2): xw = x @ w_new,
//   xs = xw*dinv[row] -> scratch; out[row] = xs*dinv[row] (self-loop init).
// 128x128 tile per block, 8 rows x 8 cols per thread, cols held as 4 f32x2.
// ---------------------------------------------------------------------------
__global__ void __launch_bounds__(256, 2)
k_gemm(const float* __restrict__ x, float* __restrict__ out) {
    extern __shared__ float Ws[];   // 128*128 floats = 64KB

    {
        float4* Ws4 = (float4*)Ws;
        const float4* W4 = (const float4*)g_wnew;
        for (int i = threadIdx.x; i < (C_DIM * C_DIM) / 4; i += 256)
            Ws4[i] = W4[i];
    }
    __syncthreads();

    const int tx = threadIdx.x & 15;          // col group
    const int ty = threadIdx.x >> 4;          // row group
    const int row0 = blockIdx.x * 128 + ty * 8;
    const int col0 = tx * 8;

    const float* xp[8];
#pragma unroll
    for (int i = 0; i < 8; i++) {
        int r = row0 + i;
        if (r >= N_NODES) r = N_NODES - 1;    // clamp (stores guarded later)
        xp[i] = x + (size_t)r * C_DIM;
    }

    u64 acc[8][4];
#pragma unroll
    for (int i = 0; i < 8; i++)
#pragma unroll
        for (int j = 0; j < 4; j++) acc[i][j] = 0ull;

    for (int k0 = 0; k0 < C_DIM; k0 += 4) {
        float4 xv[8];
#pragma unroll
        for (int i = 0; i < 8; i++)
            xv[i] = *(const float4*)(xp[i] + k0);

#pragma unroll
        for (int j = 0; j < 4; j++) {
            const int k = k0 + j;
            // 8 weight cols = 4 packed f32x2, loaded as two 16B LDS
            const ulonglong2 wA = *(const ulonglong2*)(Ws + k * C_DIM + col0);
            const ulonglong2 wB = *(const ulonglong2*)(Ws + k * C_DIM + col0 + 4);
#pragma unroll
            for (int i = 0; i < 8; i++) {
                const float xk = ((const float*)&xv[i])[j];
                const u64 xkk = pack2(xk, xk);
                fma2(acc[i][0], xkk, wA.x);
                fma2(acc[i][1], xkk, wA.y);
                fma2(acc[i][2], xkk, wB.x);
                fma2(acc[i][3], xkk, wB.y);
            }
        }
    }

#pragma unroll
    for (int i = 0; i < 8; i++) {
        const int r = row0 + i;
        if (r < N_NODES) {
            const float dv = g_dinv[r];
            const float dv2 = dv * dv;
            float a[8];
#pragma unroll
            for (int j = 0; j < 4; j++) {
                const float2 f = unpack2(acc[i][j]);
                a[2 * j] = f.x;
                a[2 * j + 1] = f.y;
            }
            float4 s0, s1, o0, o1;
            s0.x = a[0] * dv; s0.y = a[1] * dv; s0.z = a[2] * dv; s0.w = a[3] * dv;
            s1.x = a[4] * dv; s1.y = a[5] * dv; s1.z = a[6] * dv; s1.w = a[7] * dv;
            o0.x = a[0] * dv2; o0.y = a[1] * dv2; o0.z = a[2] * dv2; o0.w = a[3] * dv2;
            o1.x = a[4] * dv2; o1.y = a[5] * dv2; o1.z = a[6] * dv2; o1.w = a[7] * dv2;
            *(float4*)(g_xs + (size_t)r * C_DIM + col0)     = s0;
            *(float4*)(g_xs + (size_t)r * C_DIM + col0 + 4) = s1;
            *(float4*)(out  + (size_t)r * C_DIM + col0)     = o0;  // self-loop init
            *(float4*)(out  + (size_t)r * C_DIM + col0 + 4) = o1;
        }
    }
}

// ---------------------------------------------------------------------------
// Edge scatter: out[dst] += xs[src] * dinv[dst]   (xs already holds *dinv[src])
// ---------------------------------------------------------------------------
__global__ void k_scatter(const int* __restrict__ srcA,
                          const int* __restrict__ dstA,
                          float* __restrict__ out) {
    const int warp = (blockIdx.x * blockDim.x + threadIdx.x) >> 5;
    const int lane = threadIdx.x & 31;
    const int e0 = warp * 32 + lane;

    int s = 0, d = 0;
    float nrm = 0.f;                       // 0 for out-of-range edges -> adds nothing
    if (e0 < E_EDGES) {
        s = srcA[e0];
        d = dstA[e0];
        nrm = g_dinv[d];
    }

#pragma unroll 4
    for (int i = 0; i < 32; i++) {
        const int   ss = __shfl_sync(0xffffffffu, s, i);
        const int   dd = __shfl_sync(0xffffffffu, d, i);
        const float nn = __shfl_sync(0xffffffffu, nrm, i);

        const float4 v = *(const float4*)(g_xs + (size_t)ss * C_DIM + lane * 4);
        float* p = out + (size_t)dd * C_DIM + lane * 4;
        asm volatile("red.global.add.v4.f32 [%0], {%1, %2, %3, %4};"
                     :: "l"(p), "f"(v.x * nn), "f"(v.y * nn),
                        "f"(v.z * nn), "f"(v.w * nn)
                     : "memory");
    }
}

// ---------------------------------------------------------------------------
// Launch
// inputs: 0:x[N,C] 1:edge_index[2,E] 2:weight[C,C] 3:w_ih[4C,C] 4:w_hh 5:b_ih 6:b_hh
// ---------------------------------------------------------------------------
extern "C" void kernel_launch(void* const* d_in, const int* in_sizes, int n_in,
                              void* d_out, int out_size) {
    const float* x      = (const float*)d_in[0];
    const int*   ei     = (const int*)  d_in[1];
    const float* weight = (const float*)d_in[2];
    const float* w_ih   = (const float*)d_in[3];
    const float* b_ih   = (const float*)d_in[5];
    const float* b_hh   = (const float*)d_in[6];
    float* out = (float*)d_out;

    const int* srcA = ei;
    const int* dstA = ei + E_EDGES;

    k_wnew<<<C_DIM, C_DIM>>>(weight, w_ih, b_ih, b_hh);

    k_deg_init<<<(N_NODES + 255) / 256, 256>>>();
    k_deg_count<<<(E_EDGES + 255) / 256, 256>>>(dstA);
    k_dinv<<<(N_NODES + 255) / 256, 256>>>();

    cudaFuncSetAttribute(k_gemm, cudaFuncAttributeMaxDynamicSharedMemorySize, 65536);
    k_gemm<<<(N_NODES + 127) / 128, 256, 65536>>>(x, out);

    const int warps = (E_EDGES + 31) / 32;          // 50000
    const int blocks = (warps + 7) / 8;             // 256 threads = 8 warps/block
    k_scatter<<<blocks, 256>>>(srcA, dstA, out);
}